// round 13
// baseline (speedup 1.0000x reference)
#include <cuda_runtime.h>
#include <cuda_fp16.h>

#define NN 100000
#define EE 1600000
#define ET (EE + NN)
#define GG 2048
#define NBLK ((NN + 1023) / 1024)
#define WPB 8

typedef unsigned long long u64;

// ---------------- scratch (device globals; no allocation) ----------------
__device__ __align__(16) __half g_Hh[(size_t)NN * 64];  // fp16 transformed features
__device__ __align__(16) float  g_A[(size_t)NN * 64];   // aggregated output
__device__ __align__(16) float  g_als[NN * 4];
__device__ __align__(16) float  g_ald[NN * 4];
__device__ int g_deg[NN];       // zero-initialized at load; re-zeroed by pool_kernel
__device__ int g_scan[NN];
__device__ int g_rowptr[NN];
__device__ int g_bsum[NBLK];
__device__ int g_rank[ET];      // per-edge rank within its dst bucket
__device__ int g_csrc[ET];

__device__ __forceinline__ float lrelu(float x) { return x > 0.f ? x : 0.2f * x; }

// f32x2 packed helpers (Blackwell FFMA2)
__device__ __forceinline__ u64 pack2(float x, float y) {
    u64 r; asm("mov.b64 %0,{%1,%2};" : "=l"(r) : "f"(x), "f"(y)); return r;
}
__device__ __forceinline__ void fma2(u64& d, u64 a, u64 b) {
    asm("fma.rn.f32x2 %0,%1,%2,%0;" : "+l"(d) : "l"(a), "l"(b));
}
__device__ __forceinline__ float2 unpack2(u64 v) {
    float x, y; asm("mov.b64 {%0,%1},%2;" : "=f"(x), "=f"(y) : "l"(v));
    return make_float2(x, y);
}

// ---------------- CSR build ----------------
// g_deg must be zero at entry: zero-init at load, re-zeroed by pool_kernel.
__global__ void hist_kernel(const int* __restrict__ ei) {
    int i = blockIdx.x * blockDim.x + threadIdx.x;
    if (i >= ET) return;
    int dst = (i < EE) ? ei[EE + i] : (i - EE);
    g_rank[i] = atomicAdd(&g_deg[dst], 1);
}

// shfl-based inclusive block scan (1024 threads, 2 barriers)
__global__ void scan1_kernel() {
    __shared__ int wsum[32];
    int t = threadIdx.x;
    int i = blockIdx.x * 1024 + t;
    int lane = t & 31, wid = t >> 5;
    int v = (i < NN) ? g_deg[i] : 0;
    int s = v;
#pragma unroll
    for (int off = 1; off < 32; off <<= 1) {
        int u = __shfl_up_sync(0xFFFFFFFFu, s, off);
        if (lane >= off) s += u;
    }
    if (lane == 31) wsum[wid] = s;
    __syncthreads();
    if (wid == 0) {
        int ws = wsum[lane];
#pragma unroll
        for (int off = 1; off < 32; off <<= 1) {
            int u = __shfl_up_sync(0xFFFFFFFFu, ws, off);
            if (lane >= off) ws += u;
        }
        wsum[lane] = ws;
    }
    __syncthreads();
    if (wid > 0) s += wsum[wid - 1];
    if (i < NN) g_scan[i] = s;
    if (t == 1023) g_bsum[blockIdx.x] = s;
}

// scatter with inline block-sum scan: computes rowptr on the fly, writes
// g_rowptr (duplicate same-value writes are benign; every node has a
// self-loop so every entry is covered) and places edges atomic-free.
__global__ void scatter_kernel(const int* __restrict__ ei) {
    __shared__ int sb[128];
    __shared__ int ex[128];
    int t = threadIdx.x;
    int v0 = 0;
    if (t < 128) {
        v0 = (t < NBLK) ? g_bsum[t] : 0;
        sb[t] = v0;
    }
    __syncthreads();
    for (int off = 1; off < 128; off <<= 1) {
        int add = (t < 128 && t >= off) ? sb[t - off] : 0;
        __syncthreads();
        if (t < 128) sb[t] += add;
        __syncthreads();
    }
    if (t < 128) ex[t] = sb[t] - v0;  // exclusive block offsets
    __syncthreads();

    int i = blockIdx.x * blockDim.x + t;
    if (i >= ET) return;
    int src, dst;
    if (i < EE) { src = ei[i]; dst = ei[EE + i]; }
    else        { src = i - EE; dst = i - EE; }
    int rp = g_scan[dst] - g_deg[dst] + ex[dst >> 10];
    g_rowptr[dst] = rp;
    g_csrc[rp + g_rank[i]] = src;
}

// ---------------- fused GEMM + attention logits (register-tiled, R7) -------
// Block: 256 threads, tile 64 nodes x 64 channels, K in chunks of 64.
// Thread (c4 = tid&15, n4 = tid>>4) computes nodes [4*n4,4*n4+4) x ch [4*c4,4*c4+4).
template <int FIN, bool FROM_A>
__global__ void __launch_bounds__(256)
gemm_attn_kernel(const float* __restrict__ xin_ext,
                 const float* __restrict__ W,
                 const float* __restrict__ a_src,
                 const float* __restrict__ a_dst,
                 const float* __restrict__ pbias) {
    constexpr int NCH = FIN / 64;          // K chunks
    __shared__ __align__(16) float Ws[64 * 64];   // W chunk [k][64]
    __shared__ __align__(16) float Xt[64 * 68];   // x chunk transposed [k][node], stride 68
    __shared__ float Aat[128];                    // [0:64) a_src, [64:128) a_dst
    __shared__ float Pb[FIN];

    int tid = threadIdx.x;
    int nbase = blockIdx.x * 64;
    int c4 = tid & 15;
    int n4 = tid >> 4;

    if (tid < 64)       Aat[tid] = a_src[tid];
    else if (tid < 128) Aat[tid] = a_dst[tid - 64];
    if (FROM_A) {
        for (int i = tid; i < FIN; i += 256) Pb[i] = pbias[i];
    }

    const float* xin = FROM_A ? (const float*)g_A : xin_ext;

    u64 acc[8];
#pragma unroll
    for (int j = 0; j < 8; j++) acc[j] = 0ull;

    for (int ch = 0; ch < NCH; ch++) {
        __syncthreads();
        for (int i = tid; i < 64 * 64; i += 256) Ws[i] = W[ch * 64 * 64 + i];
        for (int idx = tid; idx < 64 * 16; idx += 256) {
            int node = idx & 63;
            int k4 = idx >> 6;
            int gn = nbase + node;
            float4 v = make_float4(0.f, 0.f, 0.f, 0.f);
            if (gn < NN)
                v = reinterpret_cast<const float4*>(xin + (size_t)gn * FIN)[ch * 16 + k4];
            if (FROM_A) {
                v.x = fmaxf(v.x + Pb[ch * 64 + 4 * k4 + 0], 0.f);
                v.y = fmaxf(v.y + Pb[ch * 64 + 4 * k4 + 1], 0.f);
                v.z = fmaxf(v.z + Pb[ch * 64 + 4 * k4 + 2], 0.f);
                v.w = fmaxf(v.w + Pb[ch * 64 + 4 * k4 + 3], 0.f);
            }
            Xt[(4 * k4 + 0) * 68 + node] = v.x;
            Xt[(4 * k4 + 1) * 68 + node] = v.y;
            Xt[(4 * k4 + 2) * 68 + node] = v.z;
            Xt[(4 * k4 + 3) * 68 + node] = v.w;
        }
        __syncthreads();

#pragma unroll 4
        for (int k = 0; k < 64; k++) {
            double2 wd = *reinterpret_cast<const double2*>(&Ws[k * 64 + c4 * 4]);
            float4 xv = *reinterpret_cast<const float4*>(&Xt[k * 68 + n4 * 4]);
            u64 w0 = (u64)__double_as_longlong(wd.x);
            u64 w1 = (u64)__double_as_longlong(wd.y);
            u64 x0 = pack2(xv.x, xv.x);
            u64 x1 = pack2(xv.y, xv.y);
            u64 x2 = pack2(xv.z, xv.z);
            u64 x3 = pack2(xv.w, xv.w);
            fma2(acc[0], x0, w0); fma2(acc[1], x0, w1);
            fma2(acc[2], x1, w0); fma2(acc[3], x1, w1);
            fma2(acc[4], x2, w0); fma2(acc[5], x2, w1);
            fma2(acc[6], x3, w0); fma2(acc[7], x3, w1);
        }
    }

    // ---- epilogue ----
    int head = c4 >> 2;
    int cq = c4 & 3;
    float As0 = Aat[c4 * 4 + 0], As1 = Aat[c4 * 4 + 1];
    float As2 = Aat[c4 * 4 + 2], As3 = Aat[c4 * 4 + 3];
    float Ad0 = Aat[64 + c4 * 4 + 0], Ad1 = Aat[64 + c4 * 4 + 1];
    float Ad2 = Aat[64 + c4 * 4 + 2], Ad3 = Aat[64 + c4 * 4 + 3];

#pragma unroll
    for (int nn = 0; nn < 4; nn++) {
        float2 lo = unpack2(acc[nn * 2 + 0]);
        float2 hi = unpack2(acc[nn * 2 + 1]);
        int gn = nbase + n4 * 4 + nn;

        if (gn < NN) {
            __half2 h0 = __floats2half2_rn(lo.x, lo.y);
            __half2 h1 = __floats2half2_rn(hi.x, hi.y);
            uint2 pk;
            pk.x = *reinterpret_cast<unsigned*>(&h0);
            pk.y = *reinterpret_cast<unsigned*>(&h1);
            *reinterpret_cast<uint2*>(g_Hh + (size_t)gn * 64 + c4 * 4) = pk;
        }

        float ss = lo.x * As0 + lo.y * As1 + hi.x * As2 + hi.y * As3;
        float dd = lo.x * Ad0 + lo.y * Ad1 + hi.x * Ad2 + hi.y * Ad3;
        ss += __shfl_xor_sync(0xFFFFFFFFu, ss, 1);
        ss += __shfl_xor_sync(0xFFFFFFFFu, ss, 2);
        dd += __shfl_xor_sync(0xFFFFFFFFu, dd, 1);
        dd += __shfl_xor_sync(0xFFFFFFFFu, dd, 2);
        if (cq == 0 && gn < NN) {
            g_als[gn * 4 + head] = ss;
            g_ald[gn * 4 + head] = dd;
        }
    }
}

// ---------------- fused softmax + aggregation (max-free, gather) -----------
// alpha = exp(lg) / sum(exp(lg)); logits are O(1) so exp cannot overflow.
__global__ void __launch_bounds__(256) gat_aggregate_kernel() {
    __shared__ int    s_s[WPB][32];
    __shared__ float4 s_w[WPB][32];

    int w = threadIdx.x >> 5;
    int lane = threadIdx.x & 31;
    int n = blockIdx.x * WPB + w;
    if (n >= NN) return;

    int beg = g_rowptr[n];
    int deg = g_deg[n];
    float4 ad = *reinterpret_cast<const float4*>(g_ald + n * 4);

    int head = lane >> 3;          // lane owns channels (2*lane, 2*lane+1)
    float accx = 0.f, accy = 0.f;
    float swh = 0.f;               // this lane's head exp-sum

    const __half2* Hp = reinterpret_cast<const __half2*>(g_Hh);

    if (deg <= 32) {
        // ---- fast path: one gather, one chunk, no max phase ----
        if (lane < deg) {
            int s_reg = g_csrc[beg + lane];
            float4 a = *reinterpret_cast<const float4*>(g_als + s_reg * 4);
            float4 wv;
            wv.x = __expf(lrelu(a.x + ad.x));
            wv.y = __expf(lrelu(a.y + ad.y));
            wv.z = __expf(lrelu(a.z + ad.z));
            wv.w = __expf(lrelu(a.w + ad.w));
            s_s[w][lane] = s_reg;
            s_w[w][lane] = wv;
        }
        __syncwarp();

        const float* wp = reinterpret_cast<const float*>(&s_w[w][0]);
#pragma unroll 8
        for (int j = 0; j < deg; j++) {
            int s0 = s_s[w][j];
            float w0 = wp[j * 4 + head];
            swh += w0;
            float2 f = __half22float2(Hp[(size_t)s0 * 32 + lane]);
            accx = fmaf(w0, f.x, accx);
            accy = fmaf(w0, f.y, accy);
        }
    } else {
        // ---- general path (rare): chunked, no max phase ----
        for (int base = 0; base < deg; base += 32) {
            int i = base + lane;
            if (i < deg) {
                int s = g_csrc[beg + i];
                float4 a = *reinterpret_cast<const float4*>(g_als + s * 4);
                float4 wv;
                wv.x = __expf(lrelu(a.x + ad.x));
                wv.y = __expf(lrelu(a.y + ad.y));
                wv.z = __expf(lrelu(a.z + ad.z));
                wv.w = __expf(lrelu(a.w + ad.w));
                s_s[w][lane] = s;
                s_w[w][lane] = wv;
            }
            __syncwarp();
            int cnt = min(32, deg - base);
            const float* wp = reinterpret_cast<const float*>(&s_w[w][0]);
#pragma unroll 8
            for (int j = 0; j < cnt; j++) {
                int s0 = s_s[w][j];
                float w0 = wp[j * 4 + head];
                swh += w0;
                float2 f = __half22float2(Hp[(size_t)s0 * 32 + lane]);
                accx = fmaf(w0, f.x, accx);
                accy = fmaf(w0, f.y, accy);
            }
            __syncwarp();
        }
    }

    float inv = 1.f / (swh + 1e-16f);
    *reinterpret_cast<float2*>(g_A + (size_t)n * 64 + 2 * lane) =
        make_float2(accx * inv, accy * inv);
}

// ---------------- output init + pooling + head ----------------
__global__ void init_out_kernel(float* out, const float* __restrict__ hb) {
    int g = blockIdx.x * blockDim.x + threadIdx.x;
    if (g < GG) out[g] = hb[0];
}

__global__ void pool_kernel(const float* __restrict__ b2,
                            const float* __restrict__ hw,
                            const int* __restrict__ batch,
                            float* out) {
    __shared__ float sb[64], sw[64];
    int tid = threadIdx.x;
    if (tid < 64) { sb[tid] = b2[tid]; sw[tid] = hw[tid]; }
    __syncthreads();

    long long t = (long long)blockIdx.x * blockDim.x + tid;
    int n = (int)(t >> 5);
    int lane = (int)(t & 31);
    if (n >= NN) return;

    const float* ar = g_A + (size_t)n * 64;
    float sm = fmaxf(ar[lane] + sb[lane], 0.f) * sw[lane]
             + fmaxf(ar[lane + 32] + sb[lane + 32], 0.f) * sw[lane + 32];
#pragma unroll
    for (int off = 16; off > 0; off >>= 1)
        sm += __shfl_down_sync(0xFFFFFFFFu, sm, off);
    if (lane == 0) {
        atomicAdd(&out[batch[n]], sm);
        g_deg[n] = 0;   // restore CSR-build invariant for the next replay
    }
}

// ---------------- launch ----------------
extern "C" void kernel_launch(void* const* d_in, const int* in_sizes, int n_in,
                              void* d_out, int out_size) {
    const float* x     = (const float*)d_in[0];
    const int*   ei    = (const int*)d_in[1];
    const int*   batch = (const int*)d_in[2];
    const float* W0  = (const float*)d_in[3];
    const float* as0 = (const float*)d_in[4];
    const float* ad0 = (const float*)d_in[5];
    const float* b0  = (const float*)d_in[6];
    const float* W1  = (const float*)d_in[7];
    const float* as1 = (const float*)d_in[8];
    const float* ad1 = (const float*)d_in[9];
    const float* b1  = (const float*)d_in[10];
    const float* W2  = (const float*)d_in[11];
    const float* as2 = (const float*)d_in[12];
    const float* ad2 = (const float*)d_in[13];
    const float* b2  = (const float*)d_in[14];
    const float* hw  = (const float*)d_in[15];
    const float* hb  = (const float*)d_in[16];
    float* out = (float*)d_out;

    const int EB = (ET + 255) / 256;
    const int GB = (NN + 63) / 64;    // 64 nodes per 256-thread block
    const int AB = (NN + WPB - 1) / WPB;
    const int PB = (int)(((long long)NN * 32 + 255) / 256);

    // CSR build (3 launches); gemm0 at capture index 3 for verification
    hist_kernel<<<EB, 256>>>(ei);                                        // 0
    scan1_kernel<<<NBLK, 1024>>>();                                      // 1
    scatter_kernel<<<EB, 256>>>(ei);                                     // 2
    gemm_attn_kernel<128, false><<<GB, 256>>>(x, W0, as0, ad0, nullptr); // 3
    gat_aggregate_kernel<<<AB, 256>>>();                                 // 4

    // layer 1 (input = g_A with bias b0 + relu)
    gemm_attn_kernel<64, true><<<GB, 256>>>(nullptr, W1, as1, ad1, b0);
    gat_aggregate_kernel<<<AB, 256>>>();

    // layer 2 (input = g_A with bias b1 + relu)
    gemm_attn_kernel<64, true><<<GB, 256>>>(nullptr, W2, as2, ad2, b1);
    gat_aggregate_kernel<<<AB, 256>>>();

    // pooling + head (bias b2 + relu fused; also re-zeros g_deg)
    init_out_kernel<<<(GG + 255) / 256, 256>>>(out, hb);
    pool_kernel<<<PB, 256>>>(b2, hw, batch, out);
}

// round 15
// speedup vs baseline: 1.2839x; 1.2839x over previous
#include <cuda_runtime.h>
#include <cuda_fp16.h>
#include <cstdint>

#define NN 100000
#define EE 1600000
#define ET (EE + NN)
#define GG 2048
#define NBLK ((NN + 1023) / 1024)
#define WPB 8
#define XSTRH 72
#define WSTRH 72

typedef unsigned long long u64;

// ---------------- scratch (device globals; no allocation) ----------------
__device__ __align__(16) __half g_Hh[(size_t)NN * 64];  // fp16 transformed features
__device__ __align__(16) float  g_A[(size_t)NN * 64];   // aggregated output
__device__ __align__(16) float  g_als[NN * 4];
__device__ __align__(16) float  g_ald[NN * 4];
__device__ int g_deg[NN];       // zero-initialized at load; re-zeroed by pool_kernel
__device__ int g_scan[NN];
__device__ int g_rowptr[NN];
__device__ int g_bsum[NBLK];
__device__ int g_rank[ET];      // per-edge rank within its dst bucket
__device__ int g_csrc[ET];

__device__ __forceinline__ float lrelu(float x) { return x > 0.f ? x : 0.2f * x; }

// ---------------- tensor-core primitives ----------------
__device__ __forceinline__ unsigned smem_u32(const void* p) {
    unsigned r;
    asm("{ .reg .u64 t; cvta.to.shared.u64 t, %1; cvt.u32.u64 %0, t; }"
        : "=r"(r) : "l"(p));
    return r;
}
__device__ __forceinline__ void ldsm_x4(unsigned& r0, unsigned& r1,
                                        unsigned& r2, unsigned& r3, unsigned a) {
    asm volatile("ldmatrix.sync.aligned.m8n8.x4.shared.b16 {%0,%1,%2,%3},[%4];"
                 : "=r"(r0), "=r"(r1), "=r"(r2), "=r"(r3) : "r"(a));
}
__device__ __forceinline__ void ldsm_x4_t(unsigned& r0, unsigned& r1,
                                          unsigned& r2, unsigned& r3, unsigned a) {
    asm volatile("ldmatrix.sync.aligned.m8n8.x4.trans.shared.b16 {%0,%1,%2,%3},[%4];"
                 : "=r"(r0), "=r"(r1), "=r"(r2), "=r"(r3) : "r"(a));
}
__device__ __forceinline__ void mma16816(float* d,
                                         unsigned a0, unsigned a1,
                                         unsigned a2, unsigned a3,
                                         unsigned b0, unsigned b1) {
    asm volatile(
        "mma.sync.aligned.m16n8k16.row.col.f32.f16.f16.f32 "
        "{%0,%1,%2,%3},{%4,%5,%6,%7},{%8,%9},{%0,%1,%2,%3};"
        : "+f"(d[0]), "+f"(d[1]), "+f"(d[2]), "+f"(d[3])
        : "r"(a0), "r"(a1), "r"(a2), "r"(a3), "r"(b0), "r"(b1));
}

// ---------------- CSR build (R11-verified) ----------------
__global__ void hist_kernel(const int* __restrict__ ei) {
    int i = blockIdx.x * blockDim.x + threadIdx.x;
    if (i >= ET) return;
    int dst = (i < EE) ? ei[EE + i] : (i - EE);
    g_rank[i] = atomicAdd(&g_deg[dst], 1);
}

__global__ void scan1_kernel() {
    __shared__ int wsum[32];
    int t = threadIdx.x;
    int i = blockIdx.x * 1024 + t;
    int lane = t & 31, wid = t >> 5;
    int v = (i < NN) ? g_deg[i] : 0;
    int s = v;
#pragma unroll
    for (int off = 1; off < 32; off <<= 1) {
        int u = __shfl_up_sync(0xFFFFFFFFu, s, off);
        if (lane >= off) s += u;
    }
    if (lane == 31) wsum[wid] = s;
    __syncthreads();
    if (wid == 0) {
        int ws = wsum[lane];
#pragma unroll
        for (int off = 1; off < 32; off <<= 1) {
            int u = __shfl_up_sync(0xFFFFFFFFu, ws, off);
            if (lane >= off) ws += u;
        }
        wsum[lane] = ws;
    }
    __syncthreads();
    if (wid > 0) s += wsum[wid - 1];
    if (i < NN) g_scan[i] = s;
    if (t == 1023) g_bsum[blockIdx.x] = s;
}

__global__ void scan3_kernel() {
    __shared__ int sb[128];
    __shared__ int ex[128];
    int t = threadIdx.x;
    int v0 = 0;
    if (t < 128) {
        v0 = (t < NBLK) ? g_bsum[t] : 0;
        sb[t] = v0;
    }
    __syncthreads();
    for (int off = 1; off < 128; off <<= 1) {
        int add = (t < 128 && t >= off) ? sb[t - off] : 0;
        __syncthreads();
        if (t < 128) sb[t] += add;
        __syncthreads();
    }
    if (t < 128) ex[t] = sb[t] - v0;
    __syncthreads();

    int i = blockIdx.x * blockDim.x + t;
    if (i >= NN) return;
    g_rowptr[i] = g_scan[i] - g_deg[i] + ex[i >> 10];
}

__global__ void scatter_kernel(const int* __restrict__ ei) {
    int i = blockIdx.x * blockDim.x + threadIdx.x;
    if (i >= ET) return;
    int src, dst;
    if (i < EE) { src = ei[i]; dst = ei[EE + i]; }
    else        { src = i - EE; dst = i - EE; }
    g_csrc[g_rowptr[dst] + g_rank[i]] = src;
}

// ---------------- fused GEMM + attention logits (HMMA tensor cores) --------
// Block: 256 threads = 8 warps; tile 128 nodes x 64 ch; K in chunks of 64.
// Warp w computes nodes [nbase+16w, +16) x all 64 ch via m16n8k16 mma.
template <int FIN, bool FROM_A>
__global__ void __launch_bounds__(256)
gemm_attn_kernel(const float* __restrict__ xin_ext,
                 const float* __restrict__ W,
                 const float* __restrict__ a_src,
                 const float* __restrict__ a_dst,
                 const float* __restrict__ pbias) {
    __shared__ __align__(16) __half Xh[128 * XSTRH];
    __shared__ __align__(16) __half Wh[64 * WSTRH];
    __shared__ float Aat[128];   // [0:64) a_src, [64:128) a_dst
    __shared__ float Pb[FIN];

    int tid = threadIdx.x;
    int w = tid >> 5, L = tid & 31;
    int nbase = blockIdx.x * 128;

    if (tid < 64)       Aat[tid] = a_src[tid];
    else if (tid < 128) Aat[tid] = a_dst[tid - 64];
    if (FROM_A) {
        for (int i = tid; i < FIN; i += 256) Pb[i] = pbias[i];
    }

    const float* xin = FROM_A ? (const float*)g_A : xin_ext;

    float acc[8][4];
#pragma unroll
    for (int nt = 0; nt < 8; nt++) {
#pragma unroll
        for (int j = 0; j < 4; j++) acc[nt][j] = 0.f;
    }

    // ldmatrix per-thread address components (canonical x4 tile order)
    int tile = L >> 3, trow = L & 7;
    int nodeoffA = (tile & 1) * 8 + trow;   // A: node row within 16
    int koffA    = (tile >> 1) * 8;         // A: k offset within 16
    int krowB    = (tile & 1) * 8 + trow;   // B: k row within 16
    int noffB    = (tile >> 1) * 8;         // B: n offset within 16

    unsigned xbase = smem_u32(Xh);
    unsigned wbase = smem_u32(Wh);

    for (int ch = 0; ch < FIN / 64; ch++) {
        __syncthreads();
        // stage W chunk [64 k][64 n] as fp16
        for (int i = tid; i < 64 * 64; i += 256) {
            int k = i >> 6, n = i & 63;
            Wh[k * WSTRH + n] = __float2half_rn(W[(ch * 64 + k) * 64 + n]);
        }
        // stage X chunk: 128 nodes x 64 k as fp16
        for (int idx = tid; idx < 128 * 16; idx += 256) {
            int node = idx & 127;
            int k4 = idx >> 7;              // 0..15
            int gn = nbase + node;
            float4 v = make_float4(0.f, 0.f, 0.f, 0.f);
            if (gn < NN)
                v = reinterpret_cast<const float4*>(xin + (size_t)gn * FIN)[ch * 16 + k4];
            if (FROM_A) {
                v.x = fmaxf(v.x + Pb[ch * 64 + 4 * k4 + 0], 0.f);
                v.y = fmaxf(v.y + Pb[ch * 64 + 4 * k4 + 1], 0.f);
                v.z = fmaxf(v.z + Pb[ch * 64 + 4 * k4 + 2], 0.f);
                v.w = fmaxf(v.w + Pb[ch * 64 + 4 * k4 + 3], 0.f);
            }
            __half2 h01 = __floats2half2_rn(v.x, v.y);
            __half2 h23 = __floats2half2_rn(v.z, v.w);
            uint2 pk;
            pk.x = *reinterpret_cast<unsigned*>(&h01);
            pk.y = *reinterpret_cast<unsigned*>(&h23);
            *reinterpret_cast<uint2*>(&Xh[node * XSTRH + k4 * 4]) = pk;
        }
        __syncthreads();

#pragma unroll
        for (int ks = 0; ks < 4; ks++) {
            unsigned a0, a1, a2, a3;
            unsigned aaddr = xbase +
                (unsigned)(((w * 16 + nodeoffA) * XSTRH + ks * 16 + koffA) * 2);
            ldsm_x4(a0, a1, a2, a3, aaddr);
#pragma unroll
            for (int p = 0; p < 4; p++) {
                unsigned c0, c1, c2, c3;
                unsigned baddr = wbase +
                    (unsigned)(((ks * 16 + krowB) * WSTRH + p * 16 + noffB) * 2);
                ldsm_x4_t(c0, c1, c2, c3, baddr);
                mma16816(acc[p * 2 + 0], a0, a1, a2, a3, c0, c1);
                mma16816(acc[p * 2 + 1], a0, a1, a2, a3, c2, c3);
            }
        }
    }

    // ---- epilogue: H fp16 store + per-head logits ----
    int r = L >> 2, q = L & 3;
    int node0 = nbase + w * 16 + r;
    int node1 = node0 + 8;
    float ss0[4] = {0.f, 0.f, 0.f, 0.f};
    float dd0[4] = {0.f, 0.f, 0.f, 0.f};
    float ss1[4] = {0.f, 0.f, 0.f, 0.f};
    float dd1[4] = {0.f, 0.f, 0.f, 0.f};

#pragma unroll
    for (int nt = 0; nt < 8; nt++) {
        float2 As = *reinterpret_cast<const float2*>(&Aat[nt * 8 + q * 2]);
        float2 Ad = *reinterpret_cast<const float2*>(&Aat[64 + nt * 8 + q * 2]);
        float d0 = acc[nt][0], d1 = acc[nt][1];
        float d2 = acc[nt][2], d3 = acc[nt][3];
        if (node0 < NN) {
            __half2 hv = __floats2half2_rn(d0, d1);
            *reinterpret_cast<__half2*>(&g_Hh[(size_t)node0 * 64 + nt * 8 + q * 2]) = hv;
        }
        if (node1 < NN) {
            __half2 hv = __floats2half2_rn(d2, d3);
            *reinterpret_cast<__half2*>(&g_Hh[(size_t)node1 * 64 + nt * 8 + q * 2]) = hv;
        }
        int hd = nt >> 1;
        ss0[hd] += d0 * As.x + d1 * As.y;
        dd0[hd] += d0 * Ad.x + d1 * Ad.y;
        ss1[hd] += d2 * As.x + d3 * As.y;
        dd1[hd] += d2 * Ad.x + d3 * Ad.y;
    }
#pragma unroll
    for (int hd = 0; hd < 4; hd++) {
        ss0[hd] += __shfl_xor_sync(0xFFFFFFFFu, ss0[hd], 1);
        ss0[hd] += __shfl_xor_sync(0xFFFFFFFFu, ss0[hd], 2);
        dd0[hd] += __shfl_xor_sync(0xFFFFFFFFu, dd0[hd], 1);
        dd0[hd] += __shfl_xor_sync(0xFFFFFFFFu, dd0[hd], 2);
        ss1[hd] += __shfl_xor_sync(0xFFFFFFFFu, ss1[hd], 1);
        ss1[hd] += __shfl_xor_sync(0xFFFFFFFFu, ss1[hd], 2);
        dd1[hd] += __shfl_xor_sync(0xFFFFFFFFu, dd1[hd], 1);
        dd1[hd] += __shfl_xor_sync(0xFFFFFFFFu, dd1[hd], 2);
    }
    if (q == 0) {
        if (node0 < NN) {
            *reinterpret_cast<float4*>(&g_als[node0 * 4]) =
                make_float4(ss0[0], ss0[1], ss0[2], ss0[3]);
            *reinterpret_cast<float4*>(&g_ald[node0 * 4]) =
                make_float4(dd0[0], dd0[1], dd0[2], dd0[3]);
        }
        if (node1 < NN) {
            *reinterpret_cast<float4*>(&g_als[node1 * 4]) =
                make_float4(ss1[0], ss1[1], ss1[2], ss1[3]);
            *reinterpret_cast<float4*>(&g_ald[node1 * 4]) =
                make_float4(dd1[0], dd1[1], dd1[2], dd1[3]);
        }
    }
}

// ---------------- fused softmax + aggregation (max-free, gather) -----------
__global__ void __launch_bounds__(256) gat_aggregate_kernel() {
    __shared__ int    s_s[WPB][32];
    __shared__ float4 s_w[WPB][32];

    int w = threadIdx.x >> 5;
    int lane = threadIdx.x & 31;
    int n = blockIdx.x * WPB + w;
    if (n >= NN) return;

    int beg = g_rowptr[n];
    int deg = g_deg[n];
    float4 ad = *reinterpret_cast<const float4*>(g_ald + n * 4);

    int head = lane >> 3;
    float accx = 0.f, accy = 0.f;
    float swh = 0.f;

    const __half2* Hp = reinterpret_cast<const __half2*>(g_Hh);

    if (deg <= 32) {
        if (lane < deg) {
            int s_reg = g_csrc[beg + lane];
            float4 a = *reinterpret_cast<const float4*>(g_als + s_reg * 4);
            float4 wv;
            wv.x = __expf(lrelu(a.x + ad.x));
            wv.y = __expf(lrelu(a.y + ad.y));
            wv.z = __expf(lrelu(a.z + ad.z));
            wv.w = __expf(lrelu(a.w + ad.w));
            s_s[w][lane] = s_reg;
            s_w[w][lane] = wv;
        }
        __syncwarp();

        const float* wp = reinterpret_cast<const float*>(&s_w[w][0]);
#pragma unroll 8
        for (int j = 0; j < deg; j++) {
            int s0 = s_s[w][j];
            float w0 = wp[j * 4 + head];
            swh += w0;
            float2 f = __half22float2(Hp[(size_t)s0 * 32 + lane]);
            accx = fmaf(w0, f.x, accx);
            accy = fmaf(w0, f.y, accy);
        }
    } else {
        for (int base = 0; base < deg; base += 32) {
            int i = base + lane;
            if (i < deg) {
                int s = g_csrc[beg + i];
                float4 a = *reinterpret_cast<const float4*>(g_als + s * 4);
                float4 wv;
                wv.x = __expf(lrelu(a.x + ad.x));
                wv.y = __expf(lrelu(a.y + ad.y));
                wv.z = __expf(lrelu(a.z + ad.z));
                wv.w = __expf(lrelu(a.w + ad.w));
                s_s[w][lane] = s;
                s_w[w][lane] = wv;
            }
            __syncwarp();
            int cnt = min(32, deg - base);
            const float* wp = reinterpret_cast<const float*>(&s_w[w][0]);
#pragma unroll 8
            for (int j = 0; j < cnt; j++) {
                int s0 = s_s[w][j];
                float w0 = wp[j * 4 + head];
                swh += w0;
                float2 f = __half22float2(Hp[(size_t)s0 * 32 + lane]);
                accx = fmaf(w0, f.x, accx);
                accy = fmaf(w0, f.y, accy);
            }
            __syncwarp();
        }
    }

    float inv = 1.f / (swh + 1e-16f);
    *reinterpret_cast<float2*>(g_A + (size_t)n * 64 + 2 * lane) =
        make_float2(accx * inv, accy * inv);
}

// ---------------- output init + pooling + head ----------------
__global__ void init_out_kernel(float* out, const float* __restrict__ hb) {
    int g = blockIdx.x * blockDim.x + threadIdx.x;
    if (g < GG) out[g] = hb[0];
}

__global__ void pool_kernel(const float* __restrict__ b2,
                            const float* __restrict__ hw,
                            const int* __restrict__ batch,
                            float* out) {
    __shared__ float sb[64], sw[64];
    int tid = threadIdx.x;
    if (tid < 64) { sb[tid] = b2[tid]; sw[tid] = hw[tid]; }
    __syncthreads();

    long long t = (long long)blockIdx.x * blockDim.x + tid;
    int n = (int)(t >> 5);
    int lane = (int)(t & 31);
    if (n >= NN) return;

    const float* ar = g_A + (size_t)n * 64;
    float sm = fmaxf(ar[lane] + sb[lane], 0.f) * sw[lane]
             + fmaxf(ar[lane + 32] + sb[lane + 32], 0.f) * sw[lane + 32];
#pragma unroll
    for (int off = 16; off > 0; off >>= 1)
        sm += __shfl_down_sync(0xFFFFFFFFu, sm, off);
    if (lane == 0) {
        atomicAdd(&out[batch[n]], sm);
        g_deg[n] = 0;   // restore CSR-build invariant for the next replay
    }
}

// ---------------- launch ----------------
extern "C" void kernel_launch(void* const* d_in, const int* in_sizes, int n_in,
                              void* d_out, int out_size) {
    const float* x     = (const float*)d_in[0];
    const int*   ei    = (const int*)d_in[1];
    const int*   batch = (const int*)d_in[2];
    const float* W0  = (const float*)d_in[3];
    const float* as0 = (const float*)d_in[4];
    const float* ad0 = (const float*)d_in[5];
    const float* b0  = (const float*)d_in[6];
    const float* W1  = (const float*)d_in[7];
    const float* as1 = (const float*)d_in[8];
    const float* ad1 = (const float*)d_in[9];
    const float* b1  = (const float*)d_in[10];
    const float* W2  = (const float*)d_in[11];
    const float* as2 = (const float*)d_in[12];
    const float* ad2 = (const float*)d_in[13];
    const float* b2  = (const float*)d_in[14];
    const float* hw  = (const float*)d_in[15];
    const float* hb  = (const float*)d_in[16];
    float* out = (float*)d_out;

    const int EB = (ET + 255) / 256;
    const int NB = (NN + 255) / 256;
    const int GB = (NN + 127) / 128;
    const int AB = (NN + WPB - 1) / WPB;
    const int PB = (int)(((long long)NN * 32 + 255) / 256);

    hist_kernel<<<EB, 256>>>(ei);                                        // 0
    scan1_kernel<<<NBLK, 1024>>>();                                      // 1
    scan3_kernel<<<NB, 256>>>();                                         // 2
    gemm_attn_kernel<128, false><<<GB, 256>>>(x, W0, as0, ad0, nullptr); // 3
    scatter_kernel<<<EB, 256>>>(ei);                                     // 4

    gat_aggregate_kernel<<<AB, 256>>>();

    gemm_attn_kernel<64, true><<<GB, 256>>>(nullptr, W1, as1, ad1, b0);
    gat_aggregate_kernel<<<AB, 256>>>();

    gemm_attn_kernel<64, true><<<GB, 256>>>(nullptr, W2, as2, ad2, b1);
    gat_aggregate_kernel<<<AB, 256>>>();

    init_out_kernel<<<(GG + 255) / 256, 256>>>(out, hb);
    pool_kernel<<<PB, 256>>>(b2, hw, batch, out);
}